// round 7
// baseline (speedup 1.0000x reference)
#include <cuda_runtime.h>
#include <cuda_fp16.h>

#define NN 100000
#define EE 3200000
#define F_IN 100
#define HID 16
#define NC 18

// Scratch (static device arrays — zero-initialized at module load)
__device__ __align__(128) __half g_hs[NN * HID];   // fp16 messages layer 1
__device__ __align__(128) __half g_hs2[NN * HID];  // fp16 messages layer 2
__device__ __align__(128) float g_dinv[NN];
__device__ __align__(128) int   g_deg[NN];         // INVARIANT: zero at call entry
__device__ __align__(128) int   g_rowstart[NN + 1];
__device__ __align__(128) int   g_cursor[NN];
__device__ __align__(128) int   g_col[EE];         // CSR (by dst) column = src
__device__ __align__(128) int   g_btot[128];
__device__ __align__(128) int   g_boff[128];

#define SCAN_B 1024
#define SCAN_G 98   // 98*1024 = 100352 >= NN

// ---------------------------------------------------------------------------
// K1: in-degree count (int4-vectorized index loads). g_deg is zero on entry.
__global__ void k_deg(const int* __restrict__ dst, int E) {
    int t = blockIdx.x * blockDim.x + threadIdx.x;
    int e = t * 4;
    if (e + 3 < E) {
        int4 d = *(const int4*)(dst + e);
        atomicAdd(&g_deg[d.x], 1);
        atomicAdd(&g_deg[d.y], 1);
        atomicAdd(&g_deg[d.z], 1);
        atomicAdd(&g_deg[d.w], 1);
    } else {
        for (int k = e; k < E; k++) atomicAdd(&g_deg[dst[k]], 1);
    }
}

// ---------------------------------------------------------------------------
// K2a/b/c: exclusive prefix scan of deg -> rowstart (+ cursor copy)
__global__ void k_scanA() {
    __shared__ int s[SCAN_B];
    int i = blockIdx.x * SCAN_B + threadIdx.x;
    int v = (i < NN) ? g_deg[i] : 0;
    s[threadIdx.x] = v;
    __syncthreads();
    for (int off = 1; off < SCAN_B; off <<= 1) {
        int t = (threadIdx.x >= off) ? s[threadIdx.x - off] : 0;
        __syncthreads();
        s[threadIdx.x] += t;
        __syncthreads();
    }
    if (i < NN) g_rowstart[i] = s[threadIdx.x] - v;     // exclusive within block
    if (threadIdx.x == SCAN_B - 1) g_btot[blockIdx.x] = s[threadIdx.x];
}

__global__ void k_scanB() {   // 1 block, 128 threads
    __shared__ int s[128];
    int v = (threadIdx.x < SCAN_G) ? g_btot[threadIdx.x] : 0;
    s[threadIdx.x] = v;
    __syncthreads();
    for (int off = 1; off < 128; off <<= 1) {
        int t = (threadIdx.x >= off) ? s[threadIdx.x - off] : 0;
        __syncthreads();
        s[threadIdx.x] += t;
        __syncthreads();
    }
    if (threadIdx.x < SCAN_G) g_boff[threadIdx.x] = s[threadIdx.x] - v;
}

__global__ void k_scanC(int E) {
    int i = blockIdx.x * SCAN_B + threadIdx.x;
    if (i < NN) {
        int r = g_rowstart[i] + g_boff[blockIdx.x];
        g_rowstart[i] = r;
        g_cursor[i] = r;
    }
    if (i == 0) g_rowstart[NN] = E;
}

// ---------------------------------------------------------------------------
// K3: CSR fill — col[pos] = src, pos from per-dst cursor
__global__ void k_fill(const int* __restrict__ src, const int* __restrict__ dst, int E) {
    int t = blockIdx.x * blockDim.x + threadIdx.x;
    int e = t * 4;
    if (e + 3 < E) {
        int4 d = *(const int4*)(dst + e);
        int4 s = *(const int4*)(src + e);
        g_col[atomicAdd(&g_cursor[d.x], 1)] = s.x;
        g_col[atomicAdd(&g_cursor[d.y], 1)] = s.y;
        g_col[atomicAdd(&g_cursor[d.z], 1)] = s.z;
        g_col[atomicAdd(&g_cursor[d.w], 1)] = s.w;
    } else {
        for (int k = e; k < E; k++)
            g_col[atomicAdd(&g_cursor[dst[k]], 1)] = src[k];
    }
}

// ---------------------------------------------------------------------------
// K4: h0 = relu(x@W1+b1); hs = fp16(dinv * (h0@Wc0)). 64 nodes/block.
// Re-zeroes g_deg (restores invariant) — deg read uniformly BEFORE zeroing.
__global__ void k_node0(const float* __restrict__ x,
                        const float* __restrict__ W1,
                        const float* __restrict__ b1,
                        const float* __restrict__ Wc0) {
    __shared__ __align__(16) float sx[64 * F_IN];          // 25.6 KB
    __shared__ __align__(16) float sW1[F_IN * HID];        // 6.4 KB
    __shared__ __align__(16) float sWc0[HID * HID];
    __shared__ __align__(16) float sh[64 * HID];
    __shared__ __align__(16) float sb1[HID];

    int tid = threadIdx.x;
    for (int i = tid; i < F_IN * HID; i += 256) sW1[i] = W1[i];
    for (int i = tid; i < HID * HID; i += 256) sWc0[i] = Wc0[i];
    if (tid < HID) sb1[tid] = b1[tid];

    int base = blockIdx.x * 64;
    int nrows = NN - base; if (nrows > 64) nrows = 64;
    for (int i = tid; i < nrows * F_IN; i += 256)
        sx[i] = x[(long long)base * F_IN + i];
    __syncthreads();

    int ln = tid >> 2, jq = tid & 3;
    int node = base + ln;
    bool valid = (node < NN);

    if (valid) {
        float4 a = *(const float4*)&sb1[jq * 4];
        const float* xr = &sx[ln * F_IN];
#pragma unroll 4
        for (int k = 0; k < F_IN; k++) {
            float xv = xr[k];
            float4 w = *(const float4*)&sW1[k * HID + jq * 4];
            a.x += xv * w.x; a.y += xv * w.y; a.z += xv * w.z; a.w += xv * w.w;
        }
        a.x = fmaxf(a.x, 0.f); a.y = fmaxf(a.y, 0.f);
        a.z = fmaxf(a.z, 0.f); a.w = fmaxf(a.w, 0.f);
        *(float4*)&sh[ln * HID + jq * 4] = a;
    }
    __syncthreads();

    // Uniform deg read for all 4 threads of the node BEFORE anyone zeroes it.
    int d = valid ? g_deg[node] : 0;
    float dinv = rsqrtf((float)(d + 1));
    __syncwarp();
    if (valid && jq == 0) {
        g_dinv[node] = dinv;
        g_deg[node] = 0;                 // restore invariant for next call
    }

    if (valid) {
        float4 t = {0.f, 0.f, 0.f, 0.f};
        const float* hr = &sh[ln * HID];
#pragma unroll
        for (int i = 0; i < HID; i++) {
            float hv = hr[i];
            float4 w = *(const float4*)&sWc0[i * HID + jq * 4];
            t.x += hv * w.x; t.y += hv * w.y; t.z += hv * w.z; t.w += hv * w.w;
        }
        __half2 p0 = __floats2half2_rn(dinv * t.x, dinv * t.y);
        __half2 p1 = __floats2half2_rn(dinv * t.z, dinv * t.w);
        uint2 pk = { *(unsigned*)&p0, *(unsigned*)&p1 };
        *(uint2*)&g_hs[node * HID + jq * 4] = pk;   // 8B store, 8B-aligned
    }
}

// ---------------------------------------------------------------------------
// Warp-collective CSR gather over fp16 messages, fp32 accumulation.
// 2 lanes per edge: lane pair (q = lane&1) loads the two 16B halves of the
// 32B fp16 row. 32-edge chunks: all lanes load col once, then 2 rounds of
// 16 edges. Per-edge LSU ops: 1 col + 2 data = 3.
// Returns aggregate for feature f = lane (lanes 0..15 valid).
__device__ __forceinline__ float warp_gather_h(const __half* __restrict__ hs,
                                               int node, int lane) {
    int rs = g_rowstart[node];
    int re = g_rowstart[node + 1];
    int esub = lane >> 1;      // edge slot 0..15
    int q = lane & 1;          // which 16B half of the row
    float acc[8] = {0.f, 0.f, 0.f, 0.f, 0.f, 0.f, 0.f, 0.f};

    for (int b = rs; b < re; b += 32) {
        int le = b + lane;
        int c = (le < re) ? g_col[le] : 0;
        int s0 = __shfl_sync(0xffffffff, c, esub);
        int s1 = __shfl_sync(0xffffffff, c, 16 + esub);
        if (b + esub < re) {
            uint4 v = *(const uint4*)&hs[s0 * HID + q * 8];
            float2 f0 = __half22float2(*(__half2*)&v.x);
            float2 f1 = __half22float2(*(__half2*)&v.y);
            float2 f2 = __half22float2(*(__half2*)&v.z);
            float2 f3 = __half22float2(*(__half2*)&v.w);
            acc[0] += f0.x; acc[1] += f0.y; acc[2] += f1.x; acc[3] += f1.y;
            acc[4] += f2.x; acc[5] += f2.y; acc[6] += f3.x; acc[7] += f3.y;
        }
        if (b + 16 + esub < re) {
            uint4 v = *(const uint4*)&hs[s1 * HID + q * 8];
            float2 f0 = __half22float2(*(__half2*)&v.x);
            float2 f1 = __half22float2(*(__half2*)&v.y);
            float2 f2 = __half22float2(*(__half2*)&v.z);
            float2 f3 = __half22float2(*(__half2*)&v.w);
            acc[0] += f0.x; acc[1] += f0.y; acc[2] += f1.x; acc[3] += f1.y;
            acc[4] += f2.x; acc[5] += f2.y; acc[6] += f3.x; acc[7] += f3.y;
        }
    }
    // Reduce across lanes with same q (xor offsets 2,4,8,16 preserve lane&1).
#pragma unroll
    for (int off = 2; off < 32; off <<= 1) {
#pragma unroll
        for (int i = 0; i < 8; i++)
            acc[i] += __shfl_xor_sync(0xffffffff, acc[i], off);
    }
    // Redistribute: lane f (0..15) wants component (f&7) from a lane with
    // q == (f>>3); lanes 0 (q=0) and 1 (q=1) hold full sums.
    int srcl = (lane >> 3) & 1;
    float a0 = __shfl_sync(0xffffffff, acc[0], srcl);
    float a1 = __shfl_sync(0xffffffff, acc[1], srcl);
    float a2 = __shfl_sync(0xffffffff, acc[2], srcl);
    float a3 = __shfl_sync(0xffffffff, acc[3], srcl);
    float a4 = __shfl_sync(0xffffffff, acc[4], srcl);
    float a5 = __shfl_sync(0xffffffff, acc[5], srcl);
    float a6 = __shfl_sync(0xffffffff, acc[6], srcl);
    float a7 = __shfl_sync(0xffffffff, acc[7], srcl);
    int j = lane & 7;
    float lo = (j < 2) ? (j == 0 ? a0 : a1) : (j == 2 ? a2 : a3);
    float hi = (j < 6) ? (j == 4 ? a4 : a5) : (j == 6 ? a6 : a7);
    return (j < 4) ? lo : hi;
}

// ---------------------------------------------------------------------------
// K5: conv1 aggregate + relu + @Wc1 + dinv, fused. Warp per node. hs -> hs2.
__global__ void k_gather_mid(const float* __restrict__ bc,
                             const float* __restrict__ Wnext) {
    __shared__ float sW[HID * HID + 32];   // padded: lanes>=16 dead-read up to [271]
    __shared__ float sb[HID];
    int tid = threadIdx.x;
    for (int i = tid; i < HID * HID; i += 256) sW[i] = Wnext[i];
    for (int i = tid + HID * HID; i < HID * HID + 32; i += 256) sW[i] = 0.f;
    if (tid < HID) sb[tid] = bc[tid];
    __syncthreads();

    int warp = tid >> 5, lane = tid & 31;
    int node = blockIdx.x * 8 + warp;     // NN % 8 == 0

    float agg = warp_gather_h(g_hs, node, lane);
    float dinv = g_dinv[node];
    float h = 0.f;
    if (lane < HID) {
        float self = __half2float(g_hs[node * HID + lane]);
        h = fmaxf(dinv * (agg + self) + sb[lane], 0.f);
    }

    float t = 0.f;
#pragma unroll
    for (int i = 0; i < HID; i++) {
        float hi = __shfl_sync(0xffffffff, h, i);
        t += hi * sW[i * HID + lane];     // lanes>=16 read padded zeros, discarded
    }
    if (lane < HID) g_hs2[node * HID + lane] = __float2half_rn(dinv * t);
}

// ---------------------------------------------------------------------------
// K6: conv2 aggregate + relu + @W2 + b2 + log_softmax. Warp per node.
__global__ void k_gather_out(const float* __restrict__ bc1,
                             const float* __restrict__ W2,
                             const float* __restrict__ b2,
                             float* __restrict__ out) {
    __shared__ float sW2[HID * NC];        // 288 floats — strided staging loop!
    __shared__ float sb2[NC];
    __shared__ float sbc[HID];
    int tid = threadIdx.x;
    for (int i = tid; i < HID * NC; i += 256) sW2[i] = W2[i];
    if (tid < NC) sb2[tid] = b2[tid];
    if (tid < HID) sbc[tid] = bc1[tid];
    __syncthreads();

    int warp = tid >> 5, lane = tid & 31;
    int node = blockIdx.x * 8 + warp;

    float agg = warp_gather_h(g_hs2, node, lane);
    float dinv = g_dinv[node];
    float h = 0.f;
    if (lane < HID) {
        float self = __half2float(g_hs2[node * HID + lane]);
        h = fmaxf(dinv * (agg + self) + sbc[lane], 0.f);
    }

    float o = (lane < NC) ? sb2[lane] : -1e30f;
#pragma unroll
    for (int i = 0; i < HID; i++) {
        float hi = __shfl_sync(0xffffffff, h, i);
        if (lane < NC) o += hi * sW2[i * NC + lane];
    }
    float m = o;
#pragma unroll
    for (int off = 16; off; off >>= 1) m = fmaxf(m, __shfl_xor_sync(0xffffffff, m, off));
    float ex = (lane < NC) ? __expf(o - m) : 0.f;
    float s = ex;
#pragma unroll
    for (int off = 16; off; off >>= 1) s += __shfl_xor_sync(0xffffffff, s, off);
    float ls = m + __logf(s);
    if (lane < NC) out[node * NC + lane] = o - ls;
}

// ---------------------------------------------------------------------------
extern "C" void kernel_launch(void* const* d_in, const int* in_sizes, int n_in,
                              void* d_out, int out_size) {
    const float* x   = (const float*)d_in[0];
    const int*   ei  = (const int*)d_in[1];     // int32 indices
    const float* W1  = (const float*)d_in[2];
    const float* b1  = (const float*)d_in[3];
    const float* Wc0 = (const float*)d_in[4];
    const float* bc0 = (const float*)d_in[5];
    const float* Wc1 = (const float*)d_in[6];
    const float* bc1 = (const float*)d_in[7];
    const float* W2  = (const float*)d_in[8];
    const float* b2  = (const float*)d_in[9];
    float* out = (float*)d_out;

    int E = in_sizes[1] / 2;            // 3200000
    const int* src = ei;
    const int* dst = ei + E;

    int eb4 = (E / 4 + 255) / 256;      // edge blocks, 4 edges/thread

    k_deg<<<eb4, 256>>>(dst, E);
    k_scanA<<<SCAN_G, SCAN_B>>>();
    k_scanB<<<1, 128>>>();
    k_scanC<<<SCAN_G, SCAN_B>>>(E);
    k_fill<<<eb4, 256>>>(src, dst, E);
    k_node0<<<(NN + 63) / 64, 256>>>(x, W1, b1, Wc0);
    k_gather_mid<<<NN / 8, 256>>>(bc0, Wc1);
    k_gather_out<<<NN / 8, 256>>>(bc1, W2, b2, out);
}

// round 8
// speedup vs baseline: 1.0521x; 1.0521x over previous
#include <cuda_runtime.h>

#define NN 100000
#define EE 3200000
#define F_IN 100
#define HID 16
#define NC 18

// Scratch (static device arrays — zero-initialized at module load)
__device__ __align__(128) float g_hs[NN * HID];    // dinv*[h@W] per node (conv input msg)
__device__ __align__(128) float g_hs2[NN * HID];   // double buffer for conv2
__device__ __align__(128) float g_dinv[NN];
__device__ __align__(128) int   g_deg[NN];         // INVARIANT: zero at call entry
__device__ __align__(128) int   g_rowstart[NN + 1];
__device__ __align__(128) int   g_cursor[NN];
__device__ __align__(128) int   g_col[EE];         // CSR (by dst) column = src
__device__ __align__(128) int   g_btot[128];

#define SCAN_B 1024
#define SCAN_G 98   // 98*1024 = 100352 >= NN

// ---------------------------------------------------------------------------
// K1: in-degree count (int4-vectorized index loads). g_deg is zero on entry.
__global__ void k_deg(const int* __restrict__ dst, int E) {
    int t = blockIdx.x * blockDim.x + threadIdx.x;
    int e = t * 4;
    if (e + 3 < E) {
        int4 d = *(const int4*)(dst + e);
        atomicAdd(&g_deg[d.x], 1);
        atomicAdd(&g_deg[d.y], 1);
        atomicAdd(&g_deg[d.z], 1);
        atomicAdd(&g_deg[d.w], 1);
    } else {
        for (int k = e; k < E; k++) atomicAdd(&g_deg[dst[k]], 1);
    }
}

// ---------------------------------------------------------------------------
// K2: per-block exclusive scan of deg -> rowstart (local), block totals out.
__global__ void k_scanA() {
    __shared__ int s[SCAN_B];
    int i = blockIdx.x * SCAN_B + threadIdx.x;
    int v = (i < NN) ? g_deg[i] : 0;
    s[threadIdx.x] = v;
    __syncthreads();
    for (int off = 1; off < SCAN_B; off <<= 1) {
        int t = (threadIdx.x >= off) ? s[threadIdx.x - off] : 0;
        __syncthreads();
        s[threadIdx.x] += t;
        __syncthreads();
    }
    if (i < NN) g_rowstart[i] = s[threadIdx.x] - v;     // exclusive within block
    if (threadIdx.x == SCAN_B - 1) g_btot[blockIdx.x] = s[threadIdx.x];
}

// K3 (merged scanB+scanC): every block redundantly scans the 98 block totals
// in smem (cheap), then applies its own exclusive offset to rowstart+cursor.
__global__ void k_scanBC(int E) {
    __shared__ int s[128];
    int tid = threadIdx.x;
    if (tid < 128) s[tid] = (tid < SCAN_G) ? g_btot[tid] : 0;
    __syncthreads();
    for (int off = 1; off < 128; off <<= 1) {
        int t = 0;
        if (tid < 128 && tid >= off) t = s[tid - off];
        __syncthreads();
        if (tid < 128) s[tid] += t;
        __syncthreads();
    }
    int boff = (blockIdx.x == 0) ? 0 : s[blockIdx.x - 1];  // excl. offset of this block
    int i = blockIdx.x * SCAN_B + tid;
    if (i < NN) {
        int r = g_rowstart[i] + boff;
        g_rowstart[i] = r;
        g_cursor[i] = r;
    }
    if (i == 0) g_rowstart[NN] = E;
}

// ---------------------------------------------------------------------------
// K4: CSR fill — col[pos] = src, pos from per-dst cursor  (PROFILED SLOT #4)
__global__ void k_fill(const int* __restrict__ src, const int* __restrict__ dst, int E) {
    int t = blockIdx.x * blockDim.x + threadIdx.x;
    int e = t * 4;
    if (e + 3 < E) {
        int4 d = *(const int4*)(dst + e);
        int4 s = *(const int4*)(src + e);
        g_col[atomicAdd(&g_cursor[d.x], 1)] = s.x;
        g_col[atomicAdd(&g_cursor[d.y], 1)] = s.y;
        g_col[atomicAdd(&g_cursor[d.z], 1)] = s.z;
        g_col[atomicAdd(&g_cursor[d.w], 1)] = s.w;
    } else {
        for (int k = e; k < E; k++)
            g_col[atomicAdd(&g_cursor[dst[k]], 1)] = src[k];
    }
}

// ---------------------------------------------------------------------------
// K5: h0 = relu(x@W1+b1); hs = dinv * (h0@Wc0). 64 nodes/block, 256 threads.
// Re-zeroes g_deg (restores invariant) — deg read uniformly BEFORE zeroing.
__global__ void k_node0(const float* __restrict__ x,
                        const float* __restrict__ W1,
                        const float* __restrict__ b1,
                        const float* __restrict__ Wc0) {
    __shared__ __align__(16) float sx[64 * F_IN];          // 25.6 KB
    __shared__ __align__(16) float sW1[F_IN * HID];        // 6.4 KB
    __shared__ __align__(16) float sWc0[HID * HID];
    __shared__ __align__(16) float sh[64 * HID];
    __shared__ __align__(16) float sb1[HID];

    int tid = threadIdx.x;
    for (int i = tid; i < F_IN * HID; i += 256) sW1[i] = W1[i];
    for (int i = tid; i < HID * HID; i += 256) sWc0[i] = Wc0[i];
    if (tid < HID) sb1[tid] = b1[tid];

    int base = blockIdx.x * 64;
    int nrows = NN - base; if (nrows > 64) nrows = 64;
    for (int i = tid; i < nrows * F_IN; i += 256)
        sx[i] = x[(long long)base * F_IN + i];
    __syncthreads();

    int ln = tid >> 2, jq = tid & 3;
    int node = base + ln;
    bool valid = (node < NN);

    if (valid) {
        float4 a = *(const float4*)&sb1[jq * 4];
        const float* xr = &sx[ln * F_IN];
#pragma unroll 4
        for (int k = 0; k < F_IN; k++) {
            float xv = xr[k];
            float4 w = *(const float4*)&sW1[k * HID + jq * 4];
            a.x += xv * w.x; a.y += xv * w.y; a.z += xv * w.z; a.w += xv * w.w;
        }
        a.x = fmaxf(a.x, 0.f); a.y = fmaxf(a.y, 0.f);
        a.z = fmaxf(a.z, 0.f); a.w = fmaxf(a.w, 0.f);
        *(float4*)&sh[ln * HID + jq * 4] = a;
    }
    __syncthreads();

    // Uniform deg read for all 4 threads of the node BEFORE anyone zeroes it.
    int d = valid ? g_deg[node] : 0;
    float dinv = rsqrtf((float)(d + 1));
    __syncwarp();
    if (valid && jq == 0) {
        g_dinv[node] = dinv;
        g_deg[node] = 0;                 // restore invariant for next call
    }

    if (valid) {
        float4 t = {0.f, 0.f, 0.f, 0.f};
        const float* hr = &sh[ln * HID];
#pragma unroll
        for (int i = 0; i < HID; i++) {
            float hv = hr[i];
            float4 w = *(const float4*)&sWc0[i * HID + jq * 4];
            t.x += hv * w.x; t.y += hv * w.y; t.z += hv * w.z; t.w += hv * w.w;
        }
        float4 o = {dinv * t.x, dinv * t.y, dinv * t.z, dinv * t.w};
        *(float4*)&g_hs[node * HID + jq * 4] = o;
    }
}

// ---------------------------------------------------------------------------
// Warp-collective CSR gather (R4's known-best 8-edge formulation).
// Lanes 0-7 load col indices; quad (lane&3) loads float4 slice of edge lane>>2.
// Returns per-lane aggregate for feature f = lane (lanes 0..15 valid).
__device__ __forceinline__ float warp_gather(const float* __restrict__ hs,
                                             int node, int lane) {
    int rs = g_rowstart[node];
    int re = g_rowstart[node + 1];
    int esub = lane >> 2, q = lane & 3;
    float4 acc = {0.f, 0.f, 0.f, 0.f};
    for (int b = rs; b < re; b += 8) {
        int c = 0;
        int le = b + (lane & 7);
        if (lane < 8 && le < re) c = g_col[le];
        int s = __shfl_sync(0xffffffff, c, esub);
        if (b + esub < re) {
            float4 v = *(const float4*)&hs[s * HID + q * 4];
            acc.x += v.x; acc.y += v.y; acc.z += v.z; acc.w += v.w;
        }
    }
#pragma unroll
    for (int off = 4; off < 32; off <<= 1) {
        acc.x += __shfl_xor_sync(0xffffffff, acc.x, off);
        acc.y += __shfl_xor_sync(0xffffffff, acc.y, off);
        acc.z += __shfl_xor_sync(0xffffffff, acc.z, off);
        acc.w += __shfl_xor_sync(0xffffffff, acc.w, off);
    }
    // redistribute: lane f wants component (f&3) of quad (f>>2)'s sum
    int q2 = lane >> 2, c2 = lane & 3;
    float ax = __shfl_sync(0xffffffff, acc.x, q2);
    float ay = __shfl_sync(0xffffffff, acc.y, q2);
    float az = __shfl_sync(0xffffffff, acc.z, q2);
    float aw = __shfl_sync(0xffffffff, acc.w, q2);
    return (c2 == 0) ? ax : (c2 == 1) ? ay : (c2 == 2) ? az : aw;
}

// ---------------------------------------------------------------------------
// K6: conv1 aggregate + relu + @Wc1 + dinv, fused. Warp per node. hs -> hs2.
__global__ void k_gather_mid(const float* __restrict__ bc,
                             const float* __restrict__ Wnext) {
    __shared__ float sW[HID * HID + 32];   // padded: lanes>=16 dead-read up to [271]
    __shared__ float sb[HID];
    int tid = threadIdx.x;
    for (int i = tid; i < HID * HID; i += 256) sW[i] = Wnext[i];
    for (int i = tid + HID * HID; i < HID * HID + 32; i += 256) sW[i] = 0.f;
    if (tid < HID) sb[tid] = bc[tid];
    __syncthreads();

    int warp = tid >> 5, lane = tid & 31;
    int node = blockIdx.x * 8 + warp;     // NN % 8 == 0

    float agg = warp_gather(g_hs, node, lane);
    float dinv = g_dinv[node];
    float h = 0.f;
    if (lane < HID)
        h = fmaxf(dinv * (agg + g_hs[node * HID + lane]) + sb[lane], 0.f);

    float t = 0.f;
#pragma unroll
    for (int i = 0; i < HID; i++) {
        float hi = __shfl_sync(0xffffffff, h, i);
        t += hi * sW[i * HID + lane];     // lanes>=16 read padded zeros, discarded
    }
    if (lane < HID) g_hs2[node * HID + lane] = dinv * t;
}

// ---------------------------------------------------------------------------
// K7: conv2 aggregate + relu + @W2 + b2 + log_softmax. Warp per node.
__global__ void k_gather_out(const float* __restrict__ bc1,
                             const float* __restrict__ W2,
                             const float* __restrict__ b2,
                             float* __restrict__ out) {
    __shared__ float sW2[HID * NC];        // 288 floats — strided staging loop!
    __shared__ float sb2[NC];
    __shared__ float sbc[HID];
    int tid = threadIdx.x;
    for (int i = tid; i < HID * NC; i += 256) sW2[i] = W2[i];
    if (tid < NC) sb2[tid] = b2[tid];
    if (tid < HID) sbc[tid] = bc1[tid];
    __syncthreads();

    int warp = tid >> 5, lane = tid & 31;
    int node = blockIdx.x * 8 + warp;

    float agg = warp_gather(g_hs2, node, lane);
    float dinv = g_dinv[node];
    float h = 0.f;
    if (lane < HID)
        h = fmaxf(dinv * (agg + g_hs2[node * HID + lane]) + sbc[lane], 0.f);

    float o = (lane < NC) ? sb2[lane] : -1e30f;
#pragma unroll
    for (int i = 0; i < HID; i++) {
        float hi = __shfl_sync(0xffffffff, h, i);
        if (lane < NC) o += hi * sW2[i * NC + lane];
    }
    float m = o;
#pragma unroll
    for (int off = 16; off; off >>= 1) m = fmaxf(m, __shfl_xor_sync(0xffffffff, m, off));
    float ex = (lane < NC) ? __expf(o - m) : 0.f;
    float s = ex;
#pragma unroll
    for (int off = 16; off; off >>= 1) s += __shfl_xor_sync(0xffffffff, s, off);
    float ls = m + __logf(s);
    if (lane < NC) out[node * NC + lane] = o - ls;
}

// ---------------------------------------------------------------------------
extern "C" void kernel_launch(void* const* d_in, const int* in_sizes, int n_in,
                              void* d_out, int out_size) {
    const float* x   = (const float*)d_in[0];
    const int*   ei  = (const int*)d_in[1];     // int32 indices
    const float* W1  = (const float*)d_in[2];
    const float* b1  = (const float*)d_in[3];
    const float* Wc0 = (const float*)d_in[4];
    const float* bc0 = (const float*)d_in[5];
    const float* Wc1 = (const float*)d_in[6];
    const float* bc1 = (const float*)d_in[7];
    const float* W2  = (const float*)d_in[8];
    const float* b2  = (const float*)d_in[9];
    float* out = (float*)d_out;

    int E = in_sizes[1] / 2;            // 3200000
    const int* src = ei;
    const int* dst = ei + E;

    int eb4 = (E / 4 + 255) / 256;      // edge blocks, 4 edges/thread

    k_deg<<<eb4, 256>>>(dst, E);                        // 1
    k_scanA<<<SCAN_G, SCAN_B>>>();                      // 2
    k_scanBC<<<SCAN_G, SCAN_B>>>(E);                    // 3
    k_fill<<<eb4, 256>>>(src, dst, E);                  // 4  <- profiled slot
    k_node0<<<(NN + 63) / 64, 256>>>(x, W1, b1, Wc0);   // 5
    k_gather_mid<<<NN / 8, 256>>>(bc0, Wc1);            // 6
    k_gather_out<<<NN / 8, 256>>>(bc1, W2, b2, out);    // 7
}